// round 11
// baseline (speedup 1.0000x reference)
#include <cuda_runtime.h>
#include <cuda_bf16.h>
#include <math.h>
#include <stdint.h>

#define BB   32
#define LL   128
#define HH   200
#define NPW  20
#define NCOL 105
#define EPSV 1e-8f
#define OUTH (BB*LL*NCOL)
#define SKT  216                     // padded K stride in elements

// ---------------- scratch (device globals; no allocation allowed) ----------
__device__ float g_cpm[BB*LL*HH];
__device__ float g_chm[BB*LL*HH];
__device__ float g_norm_p[BB*LL];
__device__ float g_norm_h[BB*LL];
__device__ float g_cos[BB*LL*LL];
__device__ float g_rowsum[BB*LL];
__device__ float g_colsum[BB*LL];
__device__ float g_amean_h[BB*LL*HH];
__device__ float g_amax_h[BB*LL*HH];
__device__ float g_amean_p[BB*LL*HH];
__device__ float g_amax_p[BB*LL*HH];
__device__ float g_len_p[BB], g_len_h[BB];
__device__ int   g_idx_p[BB], g_idx_h[BB];
// squared weights + weighted norms for all 4 w matrices
// plane order: 0=maxpool, 1=full, 2=att, 3=max_att
__device__ float g_w2[4][NPW*HH];
__device__ float g_npw_p[4][BB*LL*NPW];
__device__ float g_npw_h[4][BB*LL*NPW];
// precomputed bf16 hi/lo splits in padded SKT layout
__device__ unsigned short g_Ah[BB*LL*SKT];
__device__ unsigned short g_Al[BB*LL*SKT];
__device__ unsigned short g_Bh2[BB*LL*SKT];
__device__ unsigned short g_Bl2[BB*LL*SKT];

// ---------------- helpers ----------------
__device__ __forceinline__ float wredsum(float v) {
#pragma unroll
    for (int o = 16; o > 0; o >>= 1) v += __shfl_xor_sync(0xffffffffu, v, o);
    return v;
}
__device__ __forceinline__ void wred2(float& a, float& b) {
#pragma unroll
    for (int o = 16; o > 0; o >>= 1) {
        a += __shfl_xor_sync(0xffffffffu, a, o);
        b += __shfl_xor_sync(0xffffffffu, b, o);
    }
}
__device__ __forceinline__ uint32_t smem_u32(const void* p) {
    uint32_t a;
    asm("{ .reg .u64 t; cvta.to.shared.u64 t, %1; cvt.u32.u64 %0, t; }" : "=r"(a) : "l"(p));
    return a;
}
__device__ __forceinline__ void ldm4(uint32_t* r, uint32_t addr) {
    asm volatile("ldmatrix.sync.aligned.m8n8.x4.shared.b16 {%0,%1,%2,%3}, [%4];"
                 : "=r"(r[0]), "=r"(r[1]), "=r"(r[2]), "=r"(r[3]) : "r"(addr));
}
__device__ __forceinline__ void mma16816(float* c, const uint32_t* a, const uint32_t* b) {
    asm volatile("mma.sync.aligned.m16n8k16.row.col.f32.bf16.bf16.f32 "
                 "{%0,%1,%2,%3}, {%4,%5,%6,%7}, {%8,%9}, {%0,%1,%2,%3};"
                 : "+f"(c[0]), "+f"(c[1]), "+f"(c[2]), "+f"(c[3])
                 : "r"(a[0]), "r"(a[1]), "r"(a[2]), "r"(a[3]), "r"(b[0]), "r"(b[1]));
}
__device__ __forceinline__ void split2(float x, float y, uint32_t& hp, uint32_t& lp) {
    __nv_bfloat16 hx = __float2bfloat16(x), hy = __float2bfloat16(y);
    float rx = x - __bfloat162float(hx), ry = y - __bfloat162float(hy);
    __nv_bfloat16 lx = __float2bfloat16(rx), ly = __float2bfloat16(ry);
    hp = (uint32_t)__bfloat16_as_ushort(hx) | ((uint32_t)__bfloat16_as_ushort(hy) << 16);
    lp = (uint32_t)__bfloat16_as_ushort(lx) | ((uint32_t)__bfloat16_as_ushort(ly) << 16);
}

// ---------------- mm kernel constants ----------------
#define TILE_B (128*SKT*2)
#define OFF_A  2048
#define OFF_AL (OFF_A  + TILE_B)
#define OFF_B  (OFF_AL + TILE_B)
#define OFF_BL (OFF_B  + TILE_B)
#define SMEM_MM (OFF_BL + TILE_B)    // 223232 B dynamic smem
#define CS_STRIDE 133

// ---------------- w^2 precompute ----------------
__global__ void w2_kernel(const float* __restrict__ w_mp, const float* __restrict__ w_full,
                          const float* __restrict__ w_att, const float* __restrict__ w_maxatt) {
    int i = blockIdx.x * blockDim.x + threadIdx.x;
    if (i < NPW*HH) {
        float a = w_mp[i];     g_w2[0][i] = a*a;
        float b = w_full[i];   g_w2[1][i] = b*b;
        float c = w_att[i];    g_w2[2][i] = c*c;
        float d = w_maxatt[i]; g_w2[3][i] = d*d;
    }
}

// ---------------- lens ----------------
__global__ void lens_kernel(const float* __restrict__ mask_p,
                            const float* __restrict__ mask_h) {
    int t = threadIdx.x;
    if (t < BB) {
        float s = 0.f;
        for (int i = 0; i < LL; i++) s += mask_p[t*LL + i];
        g_len_p[t] = s;
        int id = (int)(s + 0.5f) - 1;
        g_idx_p[t] = id < 0 ? 0 : id;
    } else if (t < 2*BB) {
        int b = t - BB;
        float s = 0.f;
        for (int i = 0; i < LL; i++) s += mask_h[b*LL + i];
        g_len_h[b] = s;
        int id = (int)(s + 0.5f) - 1;
        g_idx_h[b] = id < 0 ? 0 : id;
    }
}

// ---------------- preprocess: masked ctx, norms, 4x weighted norms, splits -
__global__ void prep_kernel(const float* __restrict__ ctx_p, const float* __restrict__ mask_p,
                            const float* __restrict__ ctx_h, const float* __restrict__ mask_h) {
    int side = blockIdx.y;
    const float* ctx  = side ? ctx_h  : ctx_p;
    const float* mask = side ? mask_h : mask_p;
    float* xm  = side ? g_chm    : g_cpm;
    float* nrm = side ? g_norm_h : g_norm_p;
    unsigned short* sh = side ? g_Bh2 : g_Ah;
    unsigned short* sl = side ? g_Bl2 : g_Al;

    int warp = (blockIdx.x * blockDim.x + threadIdx.x) >> 5;
    int lane = threadIdx.x & 31;
    if (warp >= BB*LL) return;

    float m = mask[warp];
    const float* x = ctx + warp*HH;
    float vv[7];
#pragma unroll
    for (int i = 0; i < 7; i++) {
        int h = lane + 32*i;
        float val = (h < HH) ? x[h]*m : 0.f;
        vv[i] = val*val;
        if (h < HH) {
            xm[warp*HH + h] = val;
            __nv_bfloat16 hi = __float2bfloat16(val);
            __nv_bfloat16 lo = __float2bfloat16(val - __bfloat162float(hi));
            sh[warp*SKT + h] = __bfloat16_as_ushort(hi);
            sl[warp*SKT + h] = __bfloat16_as_ushort(lo);
        } else if (h < 208) {
            sh[warp*SKT + h] = 0;
            sl[warp*SKT + h] = 0;
        }
    }
    float s = 0.f;
#pragma unroll
    for (int i = 0; i < 7; i++) s += vv[i];
    s = wredsum(s);
    if (lane == 0) nrm[warp] = sqrtf(s);

#pragma unroll
    for (int mplane = 0; mplane < 4; mplane++) {
        const float* u = g_w2[mplane];
        float* dst = (side ? g_npw_h[mplane] : g_npw_p[mplane]);
        for (int k = 0; k < NPW; k++) {
            float a = 0.f;
#pragma unroll
            for (int i = 0; i < 7; i++) {
                int h = lane + 32*i;
                if (h < HH) a += u[k*HH + h]*vv[i];
            }
            a = wredsum(a);
            if (lane == 0) dst[warp*NPW + k] = sqrtf(a);
        }
    }
}

// ---------------- unified mma.sync pairwise kernel (len-bounded loads) -----
__global__ __launch_bounds__(256, 1) void mm_mma_kernel(const float* __restrict__ w_mp,
                                                        float* __restrict__ out) {
    extern __shared__ char smem[];
    uint32_t sb = smem_u32(smem);
    float* nh_s = (float*)smem;

    int b = blockIdx.x / (NPW + 1);
    int k = blockIdx.x % (NPW + 1);
    int t = threadIdx.x;
    int lane = t & 31, w = t >> 5;
    bool unit = (k == NPW);

    float lenp_f = g_len_p[b], lenh_f = g_len_h[b];
    int lenp_i = (int)(lenp_f + 0.5f), lenh_i = (int)(lenh_f + 0.5f);

    if (t < 128)
        nh_s[t] = unit ? g_norm_h[b*LL + t] : g_npw_h[0][(b*LL + t)*NPW + k];

    // ---- A tiles: copy rows < lenp, zero rows >= lenp (cols 0..207) ----
    {
        const uint4* srcH = (const uint4*)(g_Ah + b*LL*SKT);
        const uint4* srcL = (const uint4*)(g_Al + b*LL*SKT);
        for (int idx = t; idx < lenp_i*26; idx += 256) {
            int row = idx / 26, c8 = idx - row*26;
            int goff = (row*SKT)/8 + c8;
            int soff = row*(SKT*2) + c8*16;
            *(uint4*)(smem + OFF_A  + soff) = srcH[goff];
            *(uint4*)(smem + OFF_AL + soff) = srcL[goff];
        }
        uint4 z = make_uint4(0u,0u,0u,0u);
        for (int idx = t; idx < (128 - lenp_i)*26; idx += 256) {
            int row = lenp_i + idx / 26, c8 = idx - (idx/26)*26;
            int soff = row*(SKT*2) + c8*16;
            *(uint4*)(smem + OFF_A  + soff) = z;
            *(uint4*)(smem + OFF_AL + soff) = z;
        }
    }
    // ---- B tiles ----
    if (unit) {
        const uint4* srcH = (const uint4*)(g_Bh2 + b*LL*SKT);
        const uint4* srcL = (const uint4*)(g_Bl2 + b*LL*SKT);
        for (int idx = t; idx < lenh_i*26; idx += 256) {
            int row = idx / 26, c8 = idx - row*26;
            int goff = (row*SKT)/8 + c8;
            int soff = row*(SKT*2) + c8*16;
            *(uint4*)(smem + OFF_B  + soff) = srcH[goff];
            *(uint4*)(smem + OFF_BL + soff) = srcL[goff];
        }
        uint4 z = make_uint4(0u,0u,0u,0u);
        for (int idx = t; idx < (128 - lenh_i)*26; idx += 256) {
            int row = lenh_i + idx / 26, c8 = idx - (idx/26)*26;
            int soff = row*(SKT*2) + c8*16;
            *(uint4*)(smem + OFF_B  + soff) = z;
            *(uint4*)(smem + OFF_BL + soff) = z;
        }
    } else {
        if (t < 128 && t < lenh_i) {
            uint2 z2 = make_uint2(0u, 0u);
            int ro = t * (SKT*2);
            *(uint2*)(smem + OFF_B  + ro + 400) = z2; *(uint2*)(smem + OFF_B  + ro + 408) = z2;
            *(uint2*)(smem + OFF_BL + ro + 400) = z2; *(uint2*)(smem + OFF_BL + ro + 408) = z2;
        }
        const float* Bb = g_chm + b*LL*HH;
        const float* wk = w_mp + k*HH;
        for (int idx = t; idx < lenh_i*50; idx += 256) {   // 50 float4 per row (200 cols)
            int row = idx / 50, c4 = idx - row*50;
            int col = c4 * 4;
            float4 b4 = *(const float4*)(Bb + row*HH + col);
            float4 w4 = *(const float4*)(wk + col);
            b4.x *= w4.x*w4.x; b4.y *= w4.y*w4.y; b4.z *= w4.z*w4.z; b4.w *= w4.w*w4.w;
            uint32_t h01, l01, h23, l23;
            int off = row*(SKT*2) + col*2;
            split2(b4.x, b4.y, h01, l01); split2(b4.z, b4.w, h23, l23);
            *(uint2*)(smem + OFF_B  + off) = make_uint2(h01, h23);
            *(uint2*)(smem + OFF_BL + off) = make_uint2(l01, l23);
        }
        uint4 z = make_uint4(0u,0u,0u,0u);
        for (int idx = t; idx < (128 - lenh_i)*26; idx += 256) {
            int row = lenh_i + idx / 26, c8 = idx - (idx/26)*26;
            int soff = row*(SKT*2) + c8*16;
            *(uint4*)(smem + OFF_B  + soff) = z;
            *(uint4*)(smem + OFF_BL + soff) = z;
        }
    }
    __syncthreads();

    int mrow0 = (w & 3) * 32;
    int n0    = (w >> 2) * 64;

    uint32_t adA[2], adAl[2], adB[4], adBl[4];
    {
        int r = lane & 7, half = (lane >> 3) & 1, ksel = lane >> 4;
#pragma unroll
        for (int mi = 0; mi < 2; mi++) {
            int row = mrow0 + mi*16 + half*8 + r;
            uint32_t byo = (uint32_t)(row*(SKT*2) + ksel*16);
            adA[mi]  = sb + OFF_A  + byo;
            adAl[mi] = sb + OFF_AL + byo;
        }
        int sel = lane >> 3;
        int kb2 = (sel & 1) * 16;
        int rb  = (sel >> 1) * 8 + (lane & 7);
#pragma unroll
        for (int ng = 0; ng < 4; ng++) {
            int row = n0 + ng*16 + rb;
            uint32_t byo = (uint32_t)(row*(SKT*2) + kb2);
            adB[ng]  = sb + OFF_B  + byo;
            adBl[ng] = sb + OFF_BL + byo;
        }
    }

    float acc[2][8][4];
#pragma unroll
    for (int mi = 0; mi < 2; mi++)
#pragma unroll
        for (int nt = 0; nt < 8; nt++)
#pragma unroll
            for (int e = 0; e < 4; e++) acc[mi][nt][e] = 0.f;

    for (int ks = 0; ks < 13; ks++) {
        uint32_t kb = (uint32_t)ks * 32;
        uint32_t ah[2][4], al_[2][4], bh[4][4], bl[4][4];
#pragma unroll
        for (int mi = 0; mi < 2; mi++) { ldm4(ah[mi], adA[mi] + kb); ldm4(al_[mi], adAl[mi] + kb); }
#pragma unroll
        for (int ng = 0; ng < 4; ng++) { ldm4(bh[ng], adB[ng] + kb); ldm4(bl[ng], adBl[ng] + kb); }
#pragma unroll
        for (int mi = 0; mi < 2; mi++)
#pragma unroll
            for (int nt = 0; nt < 8; nt++)
                mma16816(acc[mi][nt], ah[mi],  &bh[nt>>1][(nt&1)*2]);
#pragma unroll
        for (int mi = 0; mi < 2; mi++)
#pragma unroll
            for (int nt = 0; nt < 8; nt++)
                mma16816(acc[mi][nt], al_[mi], &bh[nt>>1][(nt&1)*2]);
#pragma unroll
        for (int mi = 0; mi < 2; mi++)
#pragma unroll
            for (int nt = 0; nt < 8; nt++)
                mma16816(acc[mi][nt], ah[mi],  &bl[nt>>1][(nt&1)*2]);
    }
    __syncthreads();

    float* cs = (float*)(smem + OFF_A);

    float np4[4];
#pragma unroll
    for (int mi = 0; mi < 2; mi++)
#pragma unroll
        for (int half = 0; half < 2; half++) {
            int row = mrow0 + mi*16 + half*8 + (lane >> 2);
            np4[mi*2+half] = unit ? g_norm_p[b*LL + row]
                                  : g_npw_p[0][(b*LL + row)*NPW + k];
        }
    float nh0[8], nh1[8];
#pragma unroll
    for (int nt = 0; nt < 8; nt++) {
        int c = n0 + nt*8 + (lane & 3)*2;
        nh0[nt] = nh_s[c]; nh1[nt] = nh_s[c+1];
    }
#pragma unroll
    for (int mi = 0; mi < 2; mi++)
#pragma unroll
        for (int half = 0; half < 2; half++) {
            int row = mrow0 + mi*16 + half*8 + (lane >> 2);
            float np = np4[mi*2+half];
#pragma unroll
            for (int nt = 0; nt < 8; nt++) {
                int c = n0 + nt*8 + (lane & 3)*2;
                float v0 = acc[mi][nt][half*2+0] / fmaxf(np*nh0[nt], EPSV);
                float v1 = acc[mi][nt][half*2+1] / fmaxf(np*nh1[nt], EPSV);
                cs[row*CS_STRIDE + c]     = v0;
                cs[row*CS_STRIDE + c + 1] = v1;
            }
        }
    __syncthreads();

    if (t < 128) {
        int p = t;
        float rmax = -3.0e38f, rsum = 0.f;
        for (int q = 0; q < lenh_i; q++) {
            float v = cs[p*CS_STRIDE + q];
            rsum += v;
            rmax = fmaxf(rmax, v);
        }
        bool pv = p < lenp_i;
        float* ob = out + (b*LL + p)*NCOL;
        if (unit) {
            ob[0] = pv ? rmax : 0.f;
            ob[1] = pv ? rsum/lenh_f : 0.f;
            g_rowsum[b*LL + p] = rsum;
        } else {
            ob[23 + k] = pv ? rmax : 0.f;
            ob[43 + k] = pv ? rsum/lenh_f : 0.f;
        }

        int q = t;
        float cmax = -3.0e38f, csum = 0.f;
        for (int pp = 0; pp < lenp_i; pp++) {
            float v = cs[pp*CS_STRIDE + q];
            csum += v;
            cmax = fmaxf(cmax, v);
        }
        bool qv = q < lenh_i;
        float* ob2 = out + OUTH + (b*LL + q)*NCOL;
        if (unit) {
            ob2[0] = qv ? cmax : 0.f;
            ob2[1] = qv ? csum/lenp_f : 0.f;
            g_colsum[b*LL + q] = csum;
            for (int r = 0; r < 128; r++)
                g_cos[(b*LL + r)*LL + q] = cs[r*CS_STRIDE + q];
        } else {
            ob2[23 + k] = qv ? cmax : 0.f;
            ob2[43 + k] = qv ? csum/lenp_f : 0.f;
        }
    }
}

// ---------------- attentive (16-row tiles, prefetched loads, no division) --
__global__ __launch_bounds__(224) void att_kernel() {
    __shared__ float cs[16][128];
    int side = blockIdx.y;
    int b  = blockIdx.x >> 3;
    int r0 = (blockIdx.x & 7) * 16;
    int t  = threadIdx.x;
    int lenp = (int)(g_len_p[b] + 0.5f);
    int lenh = (int)(g_len_h[b] + 0.5f);

    int len   = side ? lenp : lenh;
    const float* src = side ? (g_cpm + b*LL*HH) : (g_chm + b*LL*HH);

    if (side == 0) {
        for (int idx = t; idx < 2048; idx += 224) {
            int j = idx >> 7, q = idx & 127;
            cs[j][q] = g_cos[(b*LL + r0 + j)*LL + q];
        }
    } else {
        for (int idx = t; idx < 2048; idx += 224) {
            int p = idx >> 4, j = idx & 15;
            cs[j][p] = g_cos[(b*LL + p)*LL + r0 + j];
        }
    }
    __syncthreads();

    int h = t;
    if (h < HH) {
        float sm[16], mx[16];
#pragma unroll
        for (int j = 0; j < 16; j++) { sm[j] = 0.f; mx[j] = -3.0e38f; }
        const float* xb = src + h;

        int q = 0;
        float n0 = 0.f, n1 = 0.f, n2 = 0.f, n3 = 0.f;
        if (len >= 4) {
            n0 = xb[0];     n1 = xb[HH];
            n2 = xb[2*HH];  n3 = xb[3*HH];
        }
        for (; q + 8 <= len; q += 4) {
            float c0 = n0, c1 = n1, c2 = n2, c3 = n3;
            n0 = xb[(q+4)*HH]; n1 = xb[(q+5)*HH];
            n2 = xb[(q+6)*HH]; n3 = xb[(q+7)*HH];
#pragma unroll
            for (int j = 0; j < 16; j++) {
                float4 cv = *(const float4*)&cs[j][q];
                float v0 = c0*cv.x, v1 = c1*cv.y, v2 = c2*cv.z, v3 = c3*cv.w;
                sm[j] += (v0+v1) + (v2+v3);
                mx[j] = fmaxf(mx[j], fmaxf(fmaxf(v0,v1), fmaxf(v2,v3)));
            }
        }
        if (q + 4 <= len) {
            float c0 = n0, c1 = n1, c2 = n2, c3 = n3;
#pragma unroll
            for (int j = 0; j < 16; j++) {
                float4 cv = *(const float4*)&cs[j][q];
                float v0 = c0*cv.x, v1 = c1*cv.y, v2 = c2*cv.z, v3 = c3*cv.w;
                sm[j] += (v0+v1) + (v2+v3);
                mx[j] = fmaxf(mx[j], fmaxf(fmaxf(v0,v1), fmaxf(v2,v3)));
            }
            q += 4;
        }
        for (; q < len; q++) {
            float c0 = xb[q*HH];
#pragma unroll
            for (int j = 0; j < 16; j++) {
                float v = c0*cs[j][q];
                sm[j] += v;
                mx[j] = fmaxf(mx[j], v);
            }
        }

        if (side == 0) {
#pragma unroll
            for (int j = 0; j < 16; j++) {
                int p = r0 + j;
                g_amean_h[(b*LL + p)*HH + h] = sm[j];
                g_amax_h[(b*LL + p)*HH + h]  = (p < lenp) ? mx[j] : 0.f;
            }
        } else {
#pragma unroll
            for (int j = 0; j < 16; j++) {
                int qq = r0 + j;
                g_amean_p[(b*LL + qq)*HH + h] = sm[j];
                g_amax_p[(b*LL + qq)*HH + h]  = (qq < lenh) ? mx[j] : 0.f;
            }
        }
    }
}

// ---------------- mpm: precomputed self-norms, reduced reductions ----------
__global__ void mpm_kernel(float* __restrict__ out) {
    int side = blockIdx.y;
    int mode = blockIdx.z;
    int warp = (blockIdx.x * blockDim.x + threadIdx.x) >> 5;
    int lane = threadIdx.x & 31;
    if (warp >= BB*LL) return;
    int b = warp >> 7;
    int tok = warp & 127;

    int c1, cm;
    if (mode == 0)      { c1 = 2;  cm = 3;  }
    else if (mode == 1) { c1 = 63; cm = 64; }
    else                { c1 = 84; cm = 85; }
    float* ob = out + (side ? OUTH : 0) + warp*NCOL;

    int mylen = (int)((side ? g_len_h[b] : g_len_p[b]) + 0.5f);
    if (tok >= mylen) {
        if (lane < 21) ob[(lane == 20) ? c1 : (cm + lane)] = 0.f;
        return;
    }

    const float* v1 = (side ? g_chm : g_cpm) + warp*HH;
    int plane = mode + 1;                       // 1=full, 2=att, 3=max_att
    const float* u   = g_w2[plane];
    const float* np1 = (side ? g_npw_h[plane] : g_npw_p[plane]) + warp*NPW;
    float n1 = (side ? g_norm_h : g_norm_p)[warp];

    float a[7];
#pragma unroll
    for (int i = 0; i < 7; i++) {
        int h = lane + 32*i;
        a[i] = (h < HH) ? v1[h] : 0.f;
    }

    if (mode == 0) {
        int pidx = side ? (b*LL + g_idx_p[b]) : (b*LL + g_idx_h[b]);
        const float* v2 = (side ? g_cpm : g_chm) + pidx*HH;
        float n2 = (side ? g_norm_p : g_norm_h)[pidx];
        const float* np2 = (side ? g_npw_p[1] : g_npw_h[1]) + pidx*NPW;

        float ac[7];
#pragma unroll
        for (int i = 0; i < 7; i++) {
            int h = lane + 32*i;
            ac[i] = (h < HH) ? a[i]*v2[h] : 0.f;
        }
        float s0 = 0.f;
#pragma unroll
        for (int i = 0; i < 7; i++) s0 += ac[i];
        s0 = wredsum(s0);
        if (lane == 0) ob[c1] = s0 / fmaxf(n1*n2, EPSV);

        for (int k = 0; k < NPW; k++) {
            float t0 = 0.f;
#pragma unroll
            for (int i = 0; i < 7; i++) {
                int h = lane + 32*i;
                if (h < HH) t0 += u[k*HH + h]*ac[i];
            }
            t0 = wredsum(t0);
            if (lane == 0) ob[cm + k] = t0 / fmaxf(np1[k]*np2[k], EPSV);
        }
    } else {
        const float* v2 = ((mode == 1) ? (side ? g_amean_p : g_amean_h)
                                       : (side ? g_amax_p  : g_amax_h)) + warp*HH;
        float ac[7], cc[7];
#pragma unroll
        for (int i = 0; i < 7; i++) {
            int h = lane + 32*i;
            float c = (h < HH) ? v2[h] : 0.f;
            ac[i] = a[i]*c;
            cc[i] = c*c;
        }
        float s0 = 0.f, s2 = 0.f;
#pragma unroll
        for (int i = 0; i < 7; i++) { s0 += ac[i]; s2 += cc[i]; }
        wred2(s0, s2);
        if (lane == 0) ob[c1] = s0 / fmaxf(n1*sqrtf(s2), EPSV);

        for (int k = 0; k < NPW; k++) {
            float t0 = 0.f, t2 = 0.f;
#pragma unroll
            for (int i = 0; i < 7; i++) {
                int h = lane + 32*i;
                if (h < HH) {
                    float uw = u[k*HH + h];
                    t0 += uw*ac[i];
                    t2 += uw*cc[i];
                }
            }
            wred2(t0, t2);
            if (lane == 0) ob[cm + k] = t0 / fmaxf(np1[k]*sqrtf(t2), EPSV);
        }
    }
}

// ---------------- launch ----------------
extern "C" void kernel_launch(void* const* d_in, const int* in_sizes, int n_in,
                              void* d_out, int out_size) {
    const float* ctx_p     = (const float*)d_in[0];
    const float* mask_p    = (const float*)d_in[1];
    const float* ctx_h     = (const float*)d_in[2];
    const float* mask_h    = (const float*)d_in[3];
    const float* w_full    = (const float*)d_in[4];
    const float* w_maxpool = (const float*)d_in[5];
    const float* w_att     = (const float*)d_in[6];
    const float* w_max_att = (const float*)d_in[7];
    float* out = (float*)d_out;

    cudaFuncSetAttribute(mm_mma_kernel, cudaFuncAttributeMaxDynamicSharedMemorySize, SMEM_MM);

    w2_kernel<<<(NPW*HH + 255)/256, 256>>>(w_maxpool, w_full, w_att, w_max_att);
    lens_kernel<<<1, 64>>>(mask_p, mask_h);
    prep_kernel<<<dim3(512, 2), 256>>>(ctx_p, mask_p, ctx_h, mask_h);
    mm_mma_kernel<<<BB*(NPW+1), 256, SMEM_MM>>>(w_maxpool, out);
    att_kernel<<<dim3(256, 2), 224>>>();
    mpm_kernel<<<dim3(512, 2, 3), 256>>>(out);
}

// round 12
// speedup vs baseline: 1.1995x; 1.1995x over previous
#include <cuda_runtime.h>
#include <cuda_bf16.h>
#include <math.h>
#include <stdint.h>

#define BB   32
#define LL   128
#define HH   200
#define NPW  20
#define NCOL 105
#define EPSV 1e-8f
#define OUTH (BB*LL*NCOL)
#define SKT  216                     // padded K stride in global split layout

// ---------------- scratch (device globals; no allocation allowed) ----------
__device__ float g_cpm[BB*LL*HH];
__device__ float g_chm[BB*LL*HH];
__device__ float g_norm_p[BB*LL];
__device__ float g_norm_h[BB*LL];
__device__ float g_np_p[BB*LL*NPW];
__device__ float g_np_h[BB*LL*NPW];
__device__ float g_cos[BB*LL*LL];
__device__ float g_rowsum[BB*LL];
__device__ float g_colsum[BB*LL];
__device__ float g_amean_h[BB*LL*HH];
__device__ float g_amax_h[BB*LL*HH];
__device__ float g_amean_p[BB*LL*HH];
__device__ float g_amax_p[BB*LL*HH];
__device__ float g_len_p[BB], g_len_h[BB];
__device__ int   g_idx_p[BB], g_idx_h[BB];
// precomputed bf16 hi/lo splits in padded SKT layout
__device__ unsigned short g_Ah[BB*LL*SKT];
__device__ unsigned short g_Al[BB*LL*SKT];
__device__ unsigned short g_Bh2[BB*LL*SKT];
__device__ unsigned short g_Bl2[BB*LL*SKT];

// ---------------- helpers ----------------
__device__ __forceinline__ float wredsum(float v) {
#pragma unroll
    for (int o = 16; o > 0; o >>= 1) v += __shfl_xor_sync(0xffffffffu, v, o);
    return v;
}
__device__ __forceinline__ void wred3(float& a, float& b, float& c) {
#pragma unroll
    for (int o = 16; o > 0; o >>= 1) {
        a += __shfl_xor_sync(0xffffffffu, a, o);
        b += __shfl_xor_sync(0xffffffffu, b, o);
        c += __shfl_xor_sync(0xffffffffu, c, o);
    }
}
__device__ __forceinline__ uint32_t smem_u32(const void* p) {
    uint32_t a;
    asm("{ .reg .u64 t; cvta.to.shared.u64 t, %1; cvt.u32.u64 %0, t; }" : "=r"(a) : "l"(p));
    return a;
}
__device__ __forceinline__ void ldm4(uint32_t* r, uint32_t addr) {
    asm volatile("ldmatrix.sync.aligned.m8n8.x4.shared.b16 {%0,%1,%2,%3}, [%4];"
                 : "=r"(r[0]), "=r"(r[1]), "=r"(r[2]), "=r"(r[3]) : "r"(addr));
}
__device__ __forceinline__ void mma16816(float* c, const uint32_t* a, const uint32_t* b) {
    asm volatile("mma.sync.aligned.m16n8k16.row.col.f32.bf16.bf16.f32 "
                 "{%0,%1,%2,%3}, {%4,%5,%6,%7}, {%8,%9}, {%0,%1,%2,%3};"
                 : "+f"(c[0]), "+f"(c[1]), "+f"(c[2]), "+f"(c[3])
                 : "r"(a[0]), "r"(a[1]), "r"(a[2]), "r"(a[3]), "r"(b[0]), "r"(b[1]));
}
__device__ __forceinline__ void split2(float x, float y, uint32_t& hp, uint32_t& lp) {
    __nv_bfloat16 hx = __float2bfloat16(x), hy = __float2bfloat16(y);
    float rx = x - __bfloat162float(hx), ry = y - __bfloat162float(hy);
    __nv_bfloat16 lx = __float2bfloat16(rx), ly = __float2bfloat16(ry);
    hp = (uint32_t)__bfloat16_as_ushort(hx) | ((uint32_t)__bfloat16_as_ushort(hy) << 16);
    lp = (uint32_t)__bfloat16_as_ushort(lx) | ((uint32_t)__bfloat16_as_ushort(ly) << 16);
}

// ---------------- mm kernel constants ----------------
#define SST    88                    // stage row stride (elems); 176B rows conflict-free
#define STILE  (128*SST*2)           // 22528 B per stage tile
#define OFF_A  1024
#define OFF_AL (OFF_A  + STILE)
#define OFF_B  (OFF_AL + STILE)
#define OFF_BL (OFF_B  + STILE)
#define SMEM_MM (OFF_BL + STILE)     // 91136 B dynamic smem -> 2 CTA/SM
#define CS_STRIDE 133                // fp32 epilogue tile (68096 B, reuses tiles)

// ---------------- lens ----------------
__global__ void lens_kernel(const float* __restrict__ mask_p,
                            const float* __restrict__ mask_h) {
    int t = threadIdx.x;
    if (t < BB) {
        float s = 0.f;
        for (int i = 0; i < LL; i++) s += mask_p[t*LL + i];
        g_len_p[t] = s;
        int id = (int)(s + 0.5f) - 1;
        g_idx_p[t] = id < 0 ? 0 : id;
    } else if (t < 2*BB) {
        int b = t - BB;
        float s = 0.f;
        for (int i = 0; i < LL; i++) s += mask_h[b*LL + i];
        g_len_h[b] = s;
        int id = (int)(s + 0.5f) - 1;
        g_idx_h[b] = id < 0 ? 0 : id;
    }
}

// ---------------- preprocess (R10-proven) ----------------
__global__ void prep_kernel(const float* __restrict__ ctx_p, const float* __restrict__ mask_p,
                            const float* __restrict__ ctx_h, const float* __restrict__ mask_h,
                            const float* __restrict__ w_mp) {
    int side = blockIdx.y;
    const float* ctx  = side ? ctx_h  : ctx_p;
    const float* mask = side ? mask_h : mask_p;
    float* xm  = side ? g_chm    : g_cpm;
    float* nrm = side ? g_norm_h : g_norm_p;
    float* npl = side ? g_np_h   : g_np_p;
    unsigned short* sh = side ? g_Bh2 : g_Ah;
    unsigned short* sl = side ? g_Bl2 : g_Al;

    int warp = (blockIdx.x * blockDim.x + threadIdx.x) >> 5;
    int lane = threadIdx.x & 31;
    if (warp >= BB*LL) return;

    float m = mask[warp];
    const float* x = ctx + warp*HH;
    float v[7];
#pragma unroll
    for (int i = 0; i < 7; i++) {
        int h = lane + 32*i;
        float val = (h < HH) ? x[h]*m : 0.f;
        v[i] = val;
        if (h < HH) {
            xm[warp*HH + h] = val;
            __nv_bfloat16 hi = __float2bfloat16(val);
            __nv_bfloat16 lo = __float2bfloat16(val - __bfloat162float(hi));
            sh[warp*SKT + h] = __bfloat16_as_ushort(hi);
            sl[warp*SKT + h] = __bfloat16_as_ushort(lo);
        } else if (h < 208) {
            sh[warp*SKT + h] = 0;
            sl[warp*SKT + h] = 0;
        }
    }
    float s = 0.f;
#pragma unroll
    for (int i = 0; i < 7; i++) s += v[i]*v[i];
    s = wredsum(s);
    if (lane == 0) nrm[warp] = sqrtf(s);

    for (int k = 0; k < NPW; k++) {
        float a = 0.f;
#pragma unroll
        for (int i = 0; i < 7; i++) {
            int h = lane + 32*i;
            if (h < HH) { float w = w_mp[k*HH + h]; a += w*w*v[i]*v[i]; }
        }
        a = wredsum(a);
        if (lane == 0) npl[warp*NPW + k] = sqrtf(a);
    }
}

// ---------------- mm: 3-stage K-split, 2 CTA/SM, split pass loops ----------
__global__ __launch_bounds__(256, 2) void mm_mma_kernel(const float* __restrict__ w_mp,
                                                        float* __restrict__ out) {
    extern __shared__ char smem[];
    uint32_t sb = smem_u32(smem);
    float* nh_s = (float*)smem;

    int b = blockIdx.x / (NPW + 1);
    int k = blockIdx.x % (NPW + 1);
    int t = threadIdx.x;
    int lane = t & 31, w = t >> 5;
    bool unit = (k == NPW);

    float lenp_f = g_len_p[b], lenh_f = g_len_h[b];
    int lenp_i = (int)(lenp_f + 0.5f), lenh_i = (int)(lenh_f + 0.5f);

    if (t < 128)
        nh_s[t] = unit ? g_norm_h[b*LL + t] : g_np_h[(b*LL + t)*NPW + k];

    int mrow0 = (w & 3) * 32;
    int n0    = (w >> 2) * 64;
    uint32_t adA[2], adAl[2], adB[4], adBl[4];
    {
        int r = lane & 7, half = (lane >> 3) & 1, ksel = lane >> 4;
#pragma unroll
        for (int mi = 0; mi < 2; mi++) {
            int row = mrow0 + mi*16 + half*8 + r;
            uint32_t byo = (uint32_t)(row*(SST*2) + ksel*16);
            adA[mi]  = sb + OFF_A  + byo;
            adAl[mi] = sb + OFF_AL + byo;
        }
        int sel = lane >> 3;
        int kb2 = (sel & 1) * 16;
        int rb  = (sel >> 1) * 8 + (lane & 7);
#pragma unroll
        for (int ng = 0; ng < 4; ng++) {
            int row = n0 + ng*16 + rb;
            uint32_t byo = (uint32_t)(row*(SST*2) + kb2);
            adB[ng]  = sb + OFF_B  + byo;
            adBl[ng] = sb + OFF_BL + byo;
        }
    }

    float acc[2][8][4];
#pragma unroll
    for (int mi = 0; mi < 2; mi++)
#pragma unroll
        for (int nt = 0; nt < 8; nt++)
#pragma unroll
            for (int e = 0; e < 4; e++) acc[mi][nt][e] = 0.f;

    for (int stage = 0; stage < 3; stage++) {
        int scol = stage * 80;
        int W4   = (stage < 2) ? 10 : 6;     // uint4 per row in stage tile
        int g4   = scol >> 3;                // uint4 offset within SKT row (27/row)
        if (stage) __syncthreads();          // prior MMA reads done before overwrite

        // ---- A tiles ----
        {
            const uint4* srcH = (const uint4*)(g_Ah + b*LL*SKT);
            const uint4* srcL = (const uint4*)(g_Al + b*LL*SKT);
            for (int idx = t; idx < lenp_i*W4; idx += 256) {
                int row = idx / W4, c = idx - row*W4;
                int goff = row*27 + g4 + c;
                int soff = row*(SST*2) + c*16;
                *(uint4*)(smem + OFF_A  + soff) = srcH[goff];
                *(uint4*)(smem + OFF_AL + soff) = srcL[goff];
            }
            uint4 z = make_uint4(0u,0u,0u,0u);
            for (int idx = t; idx < (128 - lenp_i)*W4; idx += 256) {
                int row = lenp_i + idx / W4, c = idx % W4;
                int soff = row*(SST*2) + c*16;
                *(uint4*)(smem + OFF_A  + soff) = z;
                *(uint4*)(smem + OFF_AL + soff) = z;
            }
        }
        // ---- B tiles ----
        if (unit) {
            const uint4* srcH = (const uint4*)(g_Bh2 + b*LL*SKT);
            const uint4* srcL = (const uint4*)(g_Bl2 + b*LL*SKT);
            for (int idx = t; idx < lenh_i*W4; idx += 256) {
                int row = idx / W4, c = idx - row*W4;
                int goff = row*27 + g4 + c;
                int soff = row*(SST*2) + c*16;
                *(uint4*)(smem + OFF_B  + soff) = srcH[goff];
                *(uint4*)(smem + OFF_BL + soff) = srcL[goff];
            }
            uint4 z = make_uint4(0u,0u,0u,0u);
            for (int idx = t; idx < (128 - lenh_i)*W4; idx += 256) {
                int row = lenh_i + idx / W4, c = idx % W4;
                int soff = row*(SST*2) + c*16;
                *(uint4*)(smem + OFF_B  + soff) = z;
                *(uint4*)(smem + OFF_BL + soff) = z;
            }
        } else {
            int R4 = (stage < 2) ? 20 : 10;  // real float4 per row this stage
            const float* Bb = g_chm + b*LL*HH;
            const float* wk = w_mp + k*HH;
            for (int idx = t; idx < lenh_i*R4; idx += 256) {
                int row = idx / R4, c4 = idx - row*R4;
                int col = scol + c4*4;
                float4 b4 = *(const float4*)(Bb + row*HH + col);
                float4 w4 = *(const float4*)(wk + col);
                b4.x *= w4.x*w4.x; b4.y *= w4.y*w4.y; b4.z *= w4.z*w4.z; b4.w *= w4.w*w4.w;
                uint32_t h01, l01, h23, l23;
                split2(b4.x, b4.y, h01, l01); split2(b4.z, b4.w, h23, l23);
                int off = row*(SST*2) + c4*8;
                *(uint2*)(smem + OFF_B  + off) = make_uint2(h01, h23);
                *(uint2*)(smem + OFF_BL + off) = make_uint2(l01, l23);
            }
            uint4 z = make_uint4(0u,0u,0u,0u);
            if (stage == 2) {                // pad tile cols 40..47 (globals 200..207)
                for (int row = t; row < lenh_i; row += 256) {
                    int soff = row*(SST*2) + 80;
                    *(uint4*)(smem + OFF_B  + soff) = z;
                    *(uint4*)(smem + OFF_BL + soff) = z;
                }
            }
            for (int idx = t; idx < (128 - lenh_i)*W4; idx += 256) {
                int row = lenh_i + idx / W4, c = idx % W4;
                int soff = row*(SST*2) + c*16;
                *(uint4*)(smem + OFF_B  + soff) = z;
                *(uint4*)(smem + OFF_BL + soff) = z;
            }
        }
        __syncthreads();

        int NS = (stage < 2) ? 5 : 3;
        // pass 1+2: Ah*Bh + Al*Bh
        for (int ks = 0; ks < NS; ks++) {
            uint32_t kb = (uint32_t)ks * 32;
            uint32_t ah[2][4], al_[2][4], bh[4][4];
#pragma unroll
            for (int mi = 0; mi < 2; mi++) { ldm4(ah[mi], adA[mi] + kb); ldm4(al_[mi], adAl[mi] + kb); }
#pragma unroll
            for (int ng = 0; ng < 4; ng++) ldm4(bh[ng], adB[ng] + kb);
#pragma unroll
            for (int mi = 0; mi < 2; mi++)
#pragma unroll
                for (int nt = 0; nt < 8; nt++)
                    mma16816(acc[mi][nt], ah[mi],  &bh[nt>>1][(nt&1)*2]);
#pragma unroll
            for (int mi = 0; mi < 2; mi++)
#pragma unroll
                for (int nt = 0; nt < 8; nt++)
                    mma16816(acc[mi][nt], al_[mi], &bh[nt>>1][(nt&1)*2]);
        }
        // pass 3: Ah*Bl
        for (int ks = 0; ks < NS; ks++) {
            uint32_t kb = (uint32_t)ks * 32;
            uint32_t ah[2][4], bl[4][4];
#pragma unroll
            for (int mi = 0; mi < 2; mi++) ldm4(ah[mi], adA[mi] + kb);
#pragma unroll
            for (int ng = 0; ng < 4; ng++) ldm4(bl[ng], adBl[ng] + kb);
#pragma unroll
            for (int mi = 0; mi < 2; mi++)
#pragma unroll
                for (int nt = 0; nt < 8; nt++)
                    mma16816(acc[mi][nt], ah[mi], &bl[nt>>1][(nt&1)*2]);
        }
    }
    __syncthreads();

    // ---- epilogue: normalize into padded fp32 tile ----
    float* cs = (float*)(smem + OFF_A);
    float np4[4];
#pragma unroll
    for (int mi = 0; mi < 2; mi++)
#pragma unroll
        for (int half = 0; half < 2; half++) {
            int row = mrow0 + mi*16 + half*8 + (lane >> 2);
            np4[mi*2+half] = unit ? g_norm_p[b*LL + row]
                                  : g_np_p[(b*LL + row)*NPW + k];
        }
    float nh0[8], nh1[8];
#pragma unroll
    for (int nt = 0; nt < 8; nt++) {
        int c = n0 + nt*8 + (lane & 3)*2;
        nh0[nt] = nh_s[c]; nh1[nt] = nh_s[c+1];
    }
#pragma unroll
    for (int mi = 0; mi < 2; mi++)
#pragma unroll
        for (int half = 0; half < 2; half++) {
            int row = mrow0 + mi*16 + half*8 + (lane >> 2);
            float np = np4[mi*2+half];
#pragma unroll
            for (int nt = 0; nt < 8; nt++) {
                int c = n0 + nt*8 + (lane & 3)*2;
                float v0 = acc[mi][nt][half*2+0] / fmaxf(np*nh0[nt], EPSV);
                float v1 = acc[mi][nt][half*2+1] / fmaxf(np*nh1[nt], EPSV);
                cs[row*CS_STRIDE + c]     = v0;
                cs[row*CS_STRIDE + c + 1] = v1;
            }
        }
    __syncthreads();

    if (t < 128) {
        int p = t;
        float rmax = -3.0e38f, rsum = 0.f;
        for (int q = 0; q < lenh_i; q++) {
            float v = cs[p*CS_STRIDE + q];
            rsum += v;
            rmax = fmaxf(rmax, v);
        }
        bool pv = p < lenp_i;
        float* ob = out + (b*LL + p)*NCOL;
        if (unit) {
            ob[0] = pv ? rmax : 0.f;
            ob[1] = pv ? rsum/lenh_f : 0.f;
            g_rowsum[b*LL + p] = rsum;
        } else {
            ob[23 + k] = pv ? rmax : 0.f;
            ob[43 + k] = pv ? rsum/lenh_f : 0.f;
        }
    } else {
        int q = t - 128;
        float cmax = -3.0e38f, csum = 0.f;
        for (int pp = 0; pp < lenp_i; pp++) {
            float v = cs[pp*CS_STRIDE + q];
            csum += v;
            cmax = fmaxf(cmax, v);
        }
        bool qv = q < lenh_i;
        float* ob2 = out + OUTH + (b*LL + q)*NCOL;
        if (unit) {
            ob2[0] = qv ? cmax : 0.f;
            ob2[1] = qv ? csum/lenp_f : 0.f;
            g_colsum[b*LL + q] = csum;
            for (int r = 0; r < 128; r++)
                g_cos[(b*LL + r)*LL + q] = cs[r*CS_STRIDE + q];
        } else {
            ob2[23 + k] = qv ? cmax : 0.f;
            ob2[43 + k] = qv ? csum/lenp_f : 0.f;
        }
    }
}

// ---------------- attentive (R10-proven) ----------------
__global__ __launch_bounds__(224) void att_kernel() {
    __shared__ float cs[16][128];
    int side = blockIdx.y;
    int b  = blockIdx.x >> 3;
    int r0 = (blockIdx.x & 7) * 16;
    int t  = threadIdx.x;
    int lenp = (int)(g_len_p[b] + 0.5f);
    int lenh = (int)(g_len_h[b] + 0.5f);

    int len   = side ? lenp : lenh;
    const float* src = side ? (g_cpm + b*LL*HH) : (g_chm + b*LL*HH);

    if (side == 0) {
        for (int idx = t; idx < 2048; idx += 224) {
            int j = idx >> 7, q = idx & 127;
            cs[j][q] = g_cos[(b*LL + r0 + j)*LL + q];
        }
    } else {
        for (int idx = t; idx < 2048; idx += 224) {
            int p = idx >> 4, j = idx & 15;
            cs[j][p] = g_cos[(b*LL + p)*LL + r0 + j];
        }
    }
    __syncthreads();

    int h = t;
    if (h < HH) {
        float sm[16], mx[16];
#pragma unroll
        for (int j = 0; j < 16; j++) { sm[j] = 0.f; mx[j] = -3.0e38f; }
        const float* xb = src + h;

        int q = 0;
        float n0 = 0.f, n1 = 0.f, n2 = 0.f, n3 = 0.f;
        if (len >= 4) {
            n0 = xb[0];     n1 = xb[HH];
            n2 = xb[2*HH];  n3 = xb[3*HH];
        }
        for (; q + 8 <= len; q += 4) {
            float c0 = n0, c1 = n1, c2 = n2, c3 = n3;
            n0 = xb[(q+4)*HH]; n1 = xb[(q+5)*HH];
            n2 = xb[(q+6)*HH]; n3 = xb[(q+7)*HH];
#pragma unroll
            for (int j = 0; j < 16; j++) {
                float4 cv = *(const float4*)&cs[j][q];
                float v0 = c0*cv.x, v1 = c1*cv.y, v2 = c2*cv.z, v3 = c3*cv.w;
                sm[j] += (v0+v1) + (v2+v3);
                mx[j] = fmaxf(mx[j], fmaxf(fmaxf(v0,v1), fmaxf(v2,v3)));
            }
        }
        if (q + 4 <= len) {
            float c0 = n0, c1 = n1, c2 = n2, c3 = n3;
#pragma unroll
            for (int j = 0; j < 16; j++) {
                float4 cv = *(const float4*)&cs[j][q];
                float v0 = c0*cv.x, v1 = c1*cv.y, v2 = c2*cv.z, v3 = c3*cv.w;
                sm[j] += (v0+v1) + (v2+v3);
                mx[j] = fmaxf(mx[j], fmaxf(fmaxf(v0,v1), fmaxf(v2,v3)));
            }
            q += 4;
        }
        for (; q < len; q++) {
            float c0 = xb[q*HH];
#pragma unroll
            for (int j = 0; j < 16; j++) {
                float v = c0*cs[j][q];
                sm[j] += v;
                mx[j] = fmaxf(mx[j], v);
            }
        }

        if (side == 0) {
#pragma unroll
            for (int j = 0; j < 16; j++) {
                int p = r0 + j;
                g_amean_h[(b*LL + p)*HH + h] = sm[j];
                g_amax_h[(b*LL + p)*HH + h]  = (p < lenp) ? mx[j] : 0.f;
            }
        } else {
#pragma unroll
            for (int j = 0; j < 16; j++) {
                int qq = r0 + j;
                g_amean_p[(b*LL + qq)*HH + h] = sm[j];
                g_amax_p[(b*LL + qq)*HH + h]  = (qq < lenh) ? mx[j] : 0.f;
            }
        }
    }
}

// ---------------- mpm (R10-proven) ----------------
__global__ void mpm_kernel(const float* __restrict__ w_full,
                           const float* __restrict__ w_att,
                           const float* __restrict__ w_maxatt,
                           float* __restrict__ out) {
    int side = blockIdx.y;
    int mode = blockIdx.z;
    int warp = (blockIdx.x * blockDim.x + threadIdx.x) >> 5;
    int lane = threadIdx.x & 31;
    if (warp >= BB*LL) return;
    int b = warp >> 7;
    int tok = warp & 127;

    int c1, cm;
    if (mode == 0)      { c1 = 2;  cm = 3;  }
    else if (mode == 1) { c1 = 63; cm = 64; }
    else                { c1 = 84; cm = 85; }
    float* ob = out + (side ? OUTH : 0) + warp*NCOL;

    int mylen = (int)((side ? g_len_h[b] : g_len_p[b]) + 0.5f);
    if (tok >= mylen) {
        if (lane < 21) ob[(lane == 20) ? c1 : (cm + lane)] = 0.f;
        return;
    }

    const float* v1 = (side ? g_chm : g_cpm) + warp*HH;
    const float* v2;
    const float* w;
    if (mode == 0) {
        w = w_full;
        v2 = side ? (g_cpm + (b*LL + g_idx_p[b])*HH)
                  : (g_chm + (b*LL + g_idx_h[b])*HH);
    } else if (mode == 1) {
        w = w_att;
        v2 = (side ? g_amean_p : g_amean_h) + warp*HH;
    } else {
        w = w_maxatt;
        v2 = (side ? g_amax_p : g_amax_h) + warp*HH;
    }

    float a[7], c[7];
#pragma unroll
    for (int i = 0; i < 7; i++) {
        int h = lane + 32*i;
        a[i] = (h < HH) ? v1[h] : 0.f;
        c[i] = (h < HH) ? v2[h] : 0.f;
    }
    float s0 = 0.f, s1 = 0.f, s2 = 0.f;
#pragma unroll
    for (int i = 0; i < 7; i++) { s0 += a[i]*c[i]; s1 += a[i]*a[i]; s2 += c[i]*c[i]; }
    wred3(s0, s1, s2);
    if (lane == 0) ob[c1] = s0 / fmaxf(sqrtf(s1)*sqrtf(s2), EPSV);

    for (int k = 0; k < NPW; k++) {
        float t0 = 0.f, t1 = 0.f, t2 = 0.f;
#pragma unroll
        for (int i = 0; i < 7; i++) {
            int h = lane + 32*i;
            if (h < HH) {
                float wv = w[k*HH + h];
                float u = wv*wv;
                t0 += u*a[i]*c[i]; t1 += u*a[i]*a[i]; t2 += u*c[i]*c[i];
            }
        }
        wred3(t0, t1, t2);
        if (lane == 0) ob[cm + k] = t0 / fmaxf(sqrtf(t1)*sqrtf(t2), EPSV);
    }
}

// ---------------- launch ----------------
extern "C" void kernel_launch(void* const* d_in, const int* in_sizes, int n_in,
                              void* d_out, int out_size) {
    const float* ctx_p     = (const float*)d_in[0];
    const float* mask_p    = (const float*)d_in[1];
    const float* ctx_h     = (const float*)d_in[2];
    const float* mask_h    = (const float*)d_in[3];
    const float* w_full    = (const float*)d_in[4];
    const float* w_maxpool = (const float*)d_in[5];
    const float* w_att     = (const float*)d_in[6];
    const float* w_max_att = (const float*)d_in[7];
    float* out = (float*)d_out;

    cudaFuncSetAttribute(mm_mma_kernel, cudaFuncAttributeMaxDynamicSharedMemorySize, SMEM_MM);

    lens_kernel<<<1, 64>>>(mask_p, mask_h);
    prep_kernel<<<dim3(512, 2), 256>>>(ctx_p, mask_p, ctx_h, mask_h, w_maxpool);
    mm_mma_kernel<<<BB*(NPW+1), 256, SMEM_MM>>>(w_maxpool, out);
    att_kernel<<<dim3(256, 2), 224>>>();
    mpm_kernel<<<dim3(512, 2, 3), 256>>>(w_full, w_att, w_max_att, out);
}

// round 13
// speedup vs baseline: 1.2649x; 1.0545x over previous
#include <cuda_runtime.h>
#include <cuda_bf16.h>
#include <math.h>
#include <stdint.h>

#define BB   32
#define LL   128
#define HH   200
#define NPW  20
#define NCOL 105
#define EPSV 1e-8f
#define OUTH (BB*LL*NCOL)
#define SKT  216                     // padded K stride in global split layout

// ---------------- scratch (device globals; no allocation allowed) ----------
__device__ float g_cpm[BB*LL*HH];
__device__ float g_chm[BB*LL*HH];
__device__ float g_norm_p[BB*LL];
__device__ float g_norm_h[BB*LL];
__device__ float g_np_p[BB*LL*NPW];
__device__ float g_np_h[BB*LL*NPW];
__device__ float g_cos[BB*LL*LL];
__device__ float g_rowsum[BB*LL];
__device__ float g_colsum[BB*LL];
__device__ float g_amean_h[BB*LL*HH];
__device__ float g_amax_h[BB*LL*HH];
__device__ float g_amean_p[BB*LL*HH];
__device__ float g_amax_p[BB*LL*HH];
__device__ float g_len_p[BB], g_len_h[BB];
__device__ int   g_idx_p[BB], g_idx_h[BB];
// precomputed bf16 hi/lo splits in padded SKT layout
__device__ unsigned short g_Ah[BB*LL*SKT];
__device__ unsigned short g_Al[BB*LL*SKT];
__device__ unsigned short g_Bh2[BB*LL*SKT];
__device__ unsigned short g_Bl2[BB*LL*SKT];

// ---------------- helpers ----------------
__device__ __forceinline__ float wredsum(float v) {
#pragma unroll
    for (int o = 16; o > 0; o >>= 1) v += __shfl_xor_sync(0xffffffffu, v, o);
    return v;
}
__device__ __forceinline__ void wred3(float& a, float& b, float& c) {
#pragma unroll
    for (int o = 16; o > 0; o >>= 1) {
        a += __shfl_xor_sync(0xffffffffu, a, o);
        b += __shfl_xor_sync(0xffffffffu, b, o);
        c += __shfl_xor_sync(0xffffffffu, c, o);
    }
}
__device__ __forceinline__ uint32_t smem_u32(const void* p) {
    uint32_t a;
    asm("{ .reg .u64 t; cvta.to.shared.u64 t, %1; cvt.u32.u64 %0, t; }" : "=r"(a) : "l"(p));
    return a;
}
__device__ __forceinline__ void ldm4(uint32_t* r, uint32_t addr) {
    asm volatile("ldmatrix.sync.aligned.m8n8.x4.shared.b16 {%0,%1,%2,%3}, [%4];"
                 : "=r"(r[0]), "=r"(r[1]), "=r"(r[2]), "=r"(r[3]) : "r"(addr));
}
__device__ __forceinline__ void mma16816(float* c, const uint32_t* a, const uint32_t* b) {
    asm volatile("mma.sync.aligned.m16n8k16.row.col.f32.bf16.bf16.f32 "
                 "{%0,%1,%2,%3}, {%4,%5,%6,%7}, {%8,%9}, {%0,%1,%2,%3};"
                 : "+f"(c[0]), "+f"(c[1]), "+f"(c[2]), "+f"(c[3])
                 : "r"(a[0]), "r"(a[1]), "r"(a[2]), "r"(a[3]), "r"(b[0]), "r"(b[1]));
}
__device__ __forceinline__ void split2(float x, float y, uint32_t& hp, uint32_t& lp) {
    __nv_bfloat16 hx = __float2bfloat16(x), hy = __float2bfloat16(y);
    float rx = x - __bfloat162float(hx), ry = y - __bfloat162float(hy);
    __nv_bfloat16 lx = __float2bfloat16(rx), ly = __float2bfloat16(ry);
    hp = (uint32_t)__bfloat16_as_ushort(hx) | ((uint32_t)__bfloat16_as_ushort(hy) << 16);
    lp = (uint32_t)__bfloat16_as_ushort(lx) | ((uint32_t)__bfloat16_as_ushort(ly) << 16);
}
__device__ __forceinline__ void cpa16(uint32_t saddr, const void* g) {
    asm volatile("cp.async.cg.shared.global [%0], [%1], 16;" :: "r"(saddr), "l"(g));
}
#define CPA_COMMIT() asm volatile("cp.async.commit_group;" ::: "memory")
#define CPA_WAIT0()  asm volatile("cp.async.wait_group 0;" ::: "memory")

// ---------------- mm kernel constants ----------------
#define SST    88                    // stage row stride (elems); 176B rows conflict-free
#define STILE  (128*SST*2)           // 22528 B per stage tile
#define OFF_A  1024
#define OFF_AL (OFF_A  + STILE)
#define OFF_B  (OFF_AL + STILE)
#define OFF_BL (OFF_B  + STILE)
#define SMEM_MM (OFF_BL + STILE)     // 91136 B dynamic smem -> 2 CTA/SM
#define CS_STRIDE 133                // fp32 epilogue tile (reuses tiles)

// ---------------- lens ----------------
__global__ void lens_kernel(const float* __restrict__ mask_p,
                            const float* __restrict__ mask_h) {
    int t = threadIdx.x;
    if (t < BB) {
        float s = 0.f;
        for (int i = 0; i < LL; i++) s += mask_p[t*LL + i];
        g_len_p[t] = s;
        int id = (int)(s + 0.5f) - 1;
        g_idx_p[t] = id < 0 ? 0 : id;
    } else if (t < 2*BB) {
        int b = t - BB;
        float s = 0.f;
        for (int i = 0; i < LL; i++) s += mask_h[b*LL + i];
        g_len_h[b] = s;
        int id = (int)(s + 0.5f) - 1;
        g_idx_h[b] = id < 0 ? 0 : id;
    }
}

// ---------------- preprocess (R10-proven) ----------------
__global__ void prep_kernel(const float* __restrict__ ctx_p, const float* __restrict__ mask_p,
                            const float* __restrict__ ctx_h, const float* __restrict__ mask_h,
                            const float* __restrict__ w_mp) {
    int side = blockIdx.y;
    const float* ctx  = side ? ctx_h  : ctx_p;
    const float* mask = side ? mask_h : mask_p;
    float* xm  = side ? g_chm    : g_cpm;
    float* nrm = side ? g_norm_h : g_norm_p;
    float* npl = side ? g_np_h   : g_np_p;
    unsigned short* sh = side ? g_Bh2 : g_Ah;
    unsigned short* sl = side ? g_Bl2 : g_Al;

    int warp = (blockIdx.x * blockDim.x + threadIdx.x) >> 5;
    int lane = threadIdx.x & 31;
    if (warp >= BB*LL) return;

    float m = mask[warp];
    const float* x = ctx + warp*HH;
    float v[7];
#pragma unroll
    for (int i = 0; i < 7; i++) {
        int h = lane + 32*i;
        float val = (h < HH) ? x[h]*m : 0.f;
        v[i] = val;
        if (h < HH) {
            xm[warp*HH + h] = val;
            __nv_bfloat16 hi = __float2bfloat16(val);
            __nv_bfloat16 lo = __float2bfloat16(val - __bfloat162float(hi));
            sh[warp*SKT + h] = __bfloat16_as_ushort(hi);
            sl[warp*SKT + h] = __bfloat16_as_ushort(lo);
        } else if (h < 208) {
            sh[warp*SKT + h] = 0;
            sl[warp*SKT + h] = 0;
        }
    }
    float s = 0.f;
#pragma unroll
    for (int i = 0; i < 7; i++) s += v[i]*v[i];
    s = wredsum(s);
    if (lane == 0) nrm[warp] = sqrtf(s);

    for (int k = 0; k < NPW; k++) {
        float a = 0.f;
#pragma unroll
        for (int i = 0; i < 7; i++) {
            int h = lane + 32*i;
            if (h < HH) { float w = w_mp[k*HH + h]; a += w*w*v[i]*v[i]; }
        }
        a = wredsum(a);
        if (lane == 0) npl[warp*NPW + k] = sqrtf(a);
    }
}

// ---------------- mm: 3-stage K-split, 2 CTA/SM, cp.async tile copies ------
__global__ __launch_bounds__(256, 2) void mm_mma_kernel(const float* __restrict__ w_mp,
                                                        float* __restrict__ out) {
    extern __shared__ char smem[];
    uint32_t sb = smem_u32(smem);
    float* nh_s = (float*)smem;

    int b = blockIdx.x / (NPW + 1);
    int k = blockIdx.x % (NPW + 1);
    int t = threadIdx.x;
    int lane = t & 31, w = t >> 5;
    bool unit = (k == NPW);

    float lenp_f = g_len_p[b], lenh_f = g_len_h[b];
    int lenp_i = (int)(lenp_f + 0.5f), lenh_i = (int)(lenh_f + 0.5f);

    if (t < 128)
        nh_s[t] = unit ? g_norm_h[b*LL + t] : g_np_h[(b*LL + t)*NPW + k];

    int mrow0 = (w & 3) * 32;
    int n0    = (w >> 2) * 64;
    uint32_t adA[2], adAl[2], adB[4], adBl[4];
    {
        int r = lane & 7, half = (lane >> 3) & 1, ksel = lane >> 4;
#pragma unroll
        for (int mi = 0; mi < 2; mi++) {
            int row = mrow0 + mi*16 + half*8 + r;
            uint32_t byo = (uint32_t)(row*(SST*2) + ksel*16);
            adA[mi]  = sb + OFF_A  + byo;
            adAl[mi] = sb + OFF_AL + byo;
        }
        int sel = lane >> 3;
        int kb2 = (sel & 1) * 16;
        int rb  = (sel >> 1) * 8 + (lane & 7);
#pragma unroll
        for (int ng = 0; ng < 4; ng++) {
            int row = n0 + ng*16 + rb;
            uint32_t byo = (uint32_t)(row*(SST*2) + kb2);
            adB[ng]  = sb + OFF_B  + byo;
            adBl[ng] = sb + OFF_BL + byo;
        }
    }

    float acc[2][8][4];
#pragma unroll
    for (int mi = 0; mi < 2; mi++)
#pragma unroll
        for (int nt = 0; nt < 8; nt++)
#pragma unroll
            for (int e = 0; e < 4; e++) acc[mi][nt][e] = 0.f;

    for (int stage = 0; stage < 3; stage++) {
        int scol = stage * 80;
        int W4   = (stage < 2) ? 10 : 6;     // uint4 per row in stage tile
        int g4   = scol >> 3;                // uint4 offset within SKT row (27/row)
        if (stage) __syncthreads();          // prior MMA reads done before overwrite

        // ---- A tiles: cp.async raw copies (latency hidden behind B work) ----
        {
            const uint4* srcH = (const uint4*)(g_Ah + b*LL*SKT);
            const uint4* srcL = (const uint4*)(g_Al + b*LL*SKT);
            for (int idx = t; idx < lenp_i*W4; idx += 256) {
                int row = idx / W4, c = idx - row*W4;
                int goff = row*27 + g4 + c;
                int soff = row*(SST*2) + c*16;
                cpa16(sb + OFF_A  + soff, srcH + goff);
                cpa16(sb + OFF_AL + soff, srcL + goff);
            }
            uint4 z = make_uint4(0u,0u,0u,0u);
            for (int idx = t; idx < (128 - lenp_i)*W4; idx += 256) {
                int row = lenp_i + idx / W4, c = idx % W4;
                int soff = row*(SST*2) + c*16;
                *(uint4*)(smem + OFF_A  + soff) = z;
                *(uint4*)(smem + OFF_AL + soff) = z;
            }
        }
        // ---- B tiles ----
        if (unit) {
            const uint4* srcH = (const uint4*)(g_Bh2 + b*LL*SKT);
            const uint4* srcL = (const uint4*)(g_Bl2 + b*LL*SKT);
            for (int idx = t; idx < lenh_i*W4; idx += 256) {
                int row = idx / W4, c = idx - row*W4;
                int goff = row*27 + g4 + c;
                int soff = row*(SST*2) + c*16;
                cpa16(sb + OFF_B  + soff, srcH + goff);
                cpa16(sb + OFF_BL + soff, srcL + goff);
            }
            uint4 z = make_uint4(0u,0u,0u,0u);
            for (int idx = t; idx < (128 - lenh_i)*W4; idx += 256) {
                int row = lenh_i + idx / W4, c = idx % W4;
                int soff = row*(SST*2) + c*16;
                *(uint4*)(smem + OFF_B  + soff) = z;
                *(uint4*)(smem + OFF_BL + soff) = z;
            }
        } else {
            int R4 = (stage < 2) ? 20 : 10;  // real float4 per row this stage
            const float* Bb = g_chm + b*LL*HH;
            const float* wk = w_mp + k*HH;
            for (int idx = t; idx < lenh_i*R4; idx += 256) {
                int row = idx / R4, c4 = idx - row*R4;
                int col = scol + c4*4;
                float4 b4 = *(const float4*)(Bb + row*HH + col);
                float4 w4 = *(const float4*)(wk + col);
                b4.x *= w4.x*w4.x; b4.y *= w4.y*w4.y; b4.z *= w4.z*w4.z; b4.w *= w4.w*w4.w;
                uint32_t h01, l01, h23, l23;
                split2(b4.x, b4.y, h01, l01); split2(b4.z, b4.w, h23, l23);
                int off = row*(SST*2) + c4*8;
                *(uint2*)(smem + OFF_B  + off) = make_uint2(h01, h23);
                *(uint2*)(smem + OFF_BL + off) = make_uint2(l01, l23);
            }
            uint4 z = make_uint4(0u,0u,0u,0u);
            if (stage == 2) {                // pad tile cols 40..47 (globals 200..207)
                for (int row = t; row < lenh_i; row += 256) {
                    int soff = row*(SST*2) + 80;
                    *(uint4*)(smem + OFF_B  + soff) = z;
                    *(uint4*)(smem + OFF_BL + soff) = z;
                }
            }
            for (int idx = t; idx < (128 - lenh_i)*W4; idx += 256) {
                int row = lenh_i + idx / W4, c = idx % W4;
                int soff = row*(SST*2) + c*16;
                *(uint4*)(smem + OFF_B  + soff) = z;
                *(uint4*)(smem + OFF_BL + soff) = z;
            }
        }
        CPA_COMMIT();
        CPA_WAIT0();
        __syncthreads();

        int NS = (stage < 2) ? 5 : 3;
        // pass 1+2: Ah*Bh + Al*Bh
        for (int ks = 0; ks < NS; ks++) {
            uint32_t kb = (uint32_t)ks * 32;
            uint32_t ah[2][4], al_[2][4], bh[4][4];
#pragma unroll
            for (int mi = 0; mi < 2; mi++) { ldm4(ah[mi], adA[mi] + kb); ldm4(al_[mi], adAl[mi] + kb); }
#pragma unroll
            for (int ng = 0; ng < 4; ng++) ldm4(bh[ng], adB[ng] + kb);
#pragma unroll
            for (int mi = 0; mi < 2; mi++)
#pragma unroll
                for (int nt = 0; nt < 8; nt++)
                    mma16816(acc[mi][nt], ah[mi],  &bh[nt>>1][(nt&1)*2]);
#pragma unroll
            for (int mi = 0; mi < 2; mi++)
#pragma unroll
                for (int nt = 0; nt < 8; nt++)
                    mma16816(acc[mi][nt], al_[mi], &bh[nt>>1][(nt&1)*2]);
        }
        // pass 3: Ah*Bl
        for (int ks = 0; ks < NS; ks++) {
            uint32_t kb = (uint32_t)ks * 32;
            uint32_t ah[2][4], bl[4][4];
#pragma unroll
            for (int mi = 0; mi < 2; mi++) ldm4(ah[mi], adA[mi] + kb);
#pragma unroll
            for (int ng = 0; ng < 4; ng++) ldm4(bl[ng], adBl[ng] + kb);
#pragma unroll
            for (int mi = 0; mi < 2; mi++)
#pragma unroll
                for (int nt = 0; nt < 8; nt++)
                    mma16816(acc[mi][nt], ah[mi], &bl[nt>>1][(nt&1)*2]);
        }
    }
    __syncthreads();

    // ---- epilogue: normalize into padded fp32 tile ----
    float* cs = (float*)(smem + OFF_A);
    float np4[4];
#pragma unroll
    for (int mi = 0; mi < 2; mi++)
#pragma unroll
        for (int half = 0; half < 2; half++) {
            int row = mrow0 + mi*16 + half*8 + (lane >> 2);
            np4[mi*2+half] = unit ? g_norm_p[b*LL + row]
                                  : g_np_p[(b*LL + row)*NPW + k];
        }
    float nh0[8], nh1[8];
#pragma unroll
    for (int nt = 0; nt < 8; nt++) {
        int c = n0 + nt*8 + (lane & 3)*2;
        nh0[nt] = nh_s[c]; nh1[nt] = nh_s[c+1];
    }
#pragma unroll
    for (int mi = 0; mi < 2; mi++)
#pragma unroll
        for (int half = 0; half < 2; half++) {
            int row = mrow0 + mi*16 + half*8 + (lane >> 2);
            float np = np4[mi*2+half];
#pragma unroll
            for (int nt = 0; nt < 8; nt++) {
                int c = n0 + nt*8 + (lane & 3)*2;
                float v0 = acc[mi][nt][half*2+0] / fmaxf(np*nh0[nt], EPSV);
                float v1 = acc[mi][nt][half*2+1] / fmaxf(np*nh1[nt], EPSV);
                cs[row*CS_STRIDE + c]     = v0;
                cs[row*CS_STRIDE + c + 1] = v1;
            }
        }
    __syncthreads();

    if (t < 128) {
        int p = t;
        float rmax = -3.0e38f, rsum = 0.f;
        for (int q = 0; q < lenh_i; q++) {
            float v = cs[p*CS_STRIDE + q];
            rsum += v;
            rmax = fmaxf(rmax, v);
        }
        bool pv = p < lenp_i;
        float* ob = out + (b*LL + p)*NCOL;
        if (unit) {
            ob[0] = pv ? rmax : 0.f;
            ob[1] = pv ? rsum/lenh_f : 0.f;
            g_rowsum[b*LL + p] = rsum;
        } else {
            ob[23 + k] = pv ? rmax : 0.f;
            ob[43 + k] = pv ? rsum/lenh_f : 0.f;
        }
    } else {
        int q = t - 128;
        float cmax = -3.0e38f, csum = 0.f;
        for (int pp = 0; pp < lenp_i; pp++) {
            float v = cs[pp*CS_STRIDE + q];
            csum += v;
            cmax = fmaxf(cmax, v);
        }
        bool qv = q < lenh_i;
        float* ob2 = out + OUTH + (b*LL + q)*NCOL;
        if (unit) {
            ob2[0] = qv ? cmax : 0.f;
            ob2[1] = qv ? csum/lenp_f : 0.f;
            g_colsum[b*LL + q] = csum;
            for (int r = 0; r < 128; r++)
                g_cos[(b*LL + r)*LL + q] = cs[r*CS_STRIDE + q];
        } else {
            ob2[23 + k] = qv ? cmax : 0.f;
            ob2[43 + k] = qv ? csum/lenp_f : 0.f;
        }
    }
}

// ---------------- attentive (R10-proven) ----------------
__global__ __launch_bounds__(224) void att_kernel() {
    __shared__ float cs[16][128];
    int side = blockIdx.y;
    int b  = blockIdx.x >> 3;
    int r0 = (blockIdx.x & 7) * 16;
    int t  = threadIdx.x;
    int lenp = (int)(g_len_p[b] + 0.5f);
    int lenh = (int)(g_len_h[b] + 0.5f);

    int len   = side ? lenp : lenh;
    const float* src = side ? (g_cpm + b*LL*HH) : (g_chm + b*LL*HH);

    if (side == 0) {
        for (int idx = t; idx < 2048; idx += 224) {
            int j = idx >> 7, q = idx & 127;
            cs[j][q] = g_cos[(b*LL + r0 + j)*LL + q];
        }
    } else {
        for (int idx = t; idx < 2048; idx += 224) {
            int p = idx >> 4, j = idx & 15;
            cs[j][p] = g_cos[(b*LL + p)*LL + r0 + j];
        }
    }
    __syncthreads();

    int h = t;
    if (h < HH) {
        float sm[16], mx[16];
#pragma unroll
        for (int j = 0; j < 16; j++) { sm[j] = 0.f; mx[j] = -3.0e38f; }
        const float* xb = src + h;

        int q = 0;
        float n0 = 0.f, n1 = 0.f, n2 = 0.f, n3 = 0.f;
        if (len >= 4) {
            n0 = xb[0];     n1 = xb[HH];
            n2 = xb[2*HH];  n3 = xb[3*HH];
        }
        for (; q + 8 <= len; q += 4) {
            float c0 = n0, c1 = n1, c2 = n2, c3 = n3;
            n0 = xb[(q+4)*HH]; n1 = xb[(q+5)*HH];
            n2 = xb[(q+6)*HH]; n3 = xb[(q+7)*HH];
#pragma unroll
            for (int j = 0; j < 16; j++) {
                float4 cv = *(const float4*)&cs[j][q];
                float v0 = c0*cv.x, v1 = c1*cv.y, v2 = c2*cv.z, v3 = c3*cv.w;
                sm[j] += (v0+v1) + (v2+v3);
                mx[j] = fmaxf(mx[j], fmaxf(fmaxf(v0,v1), fmaxf(v2,v3)));
            }
        }
        if (q + 4 <= len) {
            float c0 = n0, c1 = n1, c2 = n2, c3 = n3;
#pragma unroll
            for (int j = 0; j < 16; j++) {
                float4 cv = *(const float4*)&cs[j][q];
                float v0 = c0*cv.x, v1 = c1*cv.y, v2 = c2*cv.z, v3 = c3*cv.w;
                sm[j] += (v0+v1) + (v2+v3);
                mx[j] = fmaxf(mx[j], fmaxf(fmaxf(v0,v1), fmaxf(v2,v3)));
            }
            q += 4;
        }
        for (; q < len; q++) {
            float c0 = xb[q*HH];
#pragma unroll
            for (int j = 0; j < 16; j++) {
                float v = c0*cs[j][q];
                sm[j] += v;
                mx[j] = fmaxf(mx[j], v);
            }
        }

        if (side == 0) {
#pragma unroll
            for (int j = 0; j < 16; j++) {
                int p = r0 + j;
                g_amean_h[(b*LL + p)*HH + h] = sm[j];
                g_amax_h[(b*LL + p)*HH + h]  = (p < lenp) ? mx[j] : 0.f;
            }
        } else {
#pragma unroll
            for (int j = 0; j < 16; j++) {
                int qq = r0 + j;
                g_amean_p[(b*LL + qq)*HH + h] = sm[j];
                g_amax_p[(b*LL + qq)*HH + h]  = (qq < lenh) ? mx[j] : 0.f;
            }
        }
    }
}

// ---------------- mpm: hoisted products, pad fast path ----------
__global__ void mpm_kernel(const float* __restrict__ w_full,
                           const float* __restrict__ w_att,
                           const float* __restrict__ w_maxatt,
                           float* __restrict__ out) {
    int side = blockIdx.y;
    int mode = blockIdx.z;
    int warp = (blockIdx.x * blockDim.x + threadIdx.x) >> 5;
    int lane = threadIdx.x & 31;
    if (warp >= BB*LL) return;
    int b = warp >> 7;
    int tok = warp & 127;

    int c1, cm;
    if (mode == 0)      { c1 = 2;  cm = 3;  }
    else if (mode == 1) { c1 = 63; cm = 64; }
    else                { c1 = 84; cm = 85; }
    float* ob = out + (side ? OUTH : 0) + warp*NCOL;

    int mylen = (int)((side ? g_len_h[b] : g_len_p[b]) + 0.5f);
    if (tok >= mylen) {
        if (lane < 21) ob[(lane == 20) ? c1 : (cm + lane)] = 0.f;
        return;
    }

    const float* v1 = (side ? g_chm : g_cpm) + warp*HH;
    const float* v2;
    const float* w;
    if (mode == 0) {
        w = w_full;
        v2 = side ? (g_cpm + (b*LL + g_idx_p[b])*HH)
                  : (g_chm + (b*LL + g_idx_h[b])*HH);
    } else if (mode == 1) {
        w = w_att;
        v2 = (side ? g_amean_p : g_amean_h) + warp*HH;
    } else {
        w = w_maxatt;
        v2 = (side ? g_amax_p : g_amax_h) + warp*HH;
    }

    float ac[7], aa[7], cc[7];
#pragma unroll
    for (int i = 0; i < 7; i++) {
        int h = lane + 32*i;
        float a = (h < HH) ? v1[h] : 0.f;
        float c = (h < HH) ? v2[h] : 0.f;
        ac[i] = a*c; aa[i] = a*a; cc[i] = c*c;
    }
    float s0 = 0.f, s1 = 0.f, s2 = 0.f;
#pragma unroll
    for (int i = 0; i < 7; i++) { s0 += ac[i]; s1 += aa[i]; s2 += cc[i]; }
    wred3(s0, s1, s2);
    if (lane == 0) ob[c1] = s0 / fmaxf(sqrtf(s1)*sqrtf(s2), EPSV);

    for (int k = 0; k < NPW; k++) {
        float t0 = 0.f, t1 = 0.f, t2 = 0.f;
#pragma unroll
        for (int i = 0; i < 7; i++) {
            int h = lane + 32*i;
            if (h < HH) {
                float wv = w[k*HH + h];
                float u = wv*wv;
                t0 += u*ac[i]; t1 += u*aa[i]; t2 += u*cc[i];
            }
        }
        wred3(t0, t1, t2);
        if (lane == 0) ob[cm + k] = t0 / fmaxf(sqrtf(t1)*sqrtf(t2), EPSV);
    }
}

// ---------------- launch ----------------
extern "C" void kernel_launch(void* const* d_in, const int* in_sizes, int n_in,
                              void* d_out, int out_size) {
    const float* ctx_p     = (const float*)d_in[0];
    const float* mask_p    = (const float*)d_in[1];
    const float* ctx_h     = (const float*)d_in[2];
    const float* mask_h    = (const float*)d_in[3];
    const float* w_full    = (const float*)d_in[4];
    const float* w_maxpool = (const float*)d_in[5];
    const float* w_att     = (const float*)d_in[6];
    const float* w_max_att = (const float*)d_in[7];
    float* out = (float*)d_out;

    cudaFuncSetAttribute(mm_mma_kernel, cudaFuncAttributeMaxDynamicSharedMemorySize, SMEM_MM);

    lens_kernel<<<1, 64>>>(mask_p, mask_h);
    prep_kernel<<<dim3(512, 2), 256>>>(ctx_p, mask_p, ctx_h, mask_h, w_maxpool);
    mm_mma_kernel<<<BB*(NPW+1), 256, SMEM_MM>>>(w_maxpool, out);
    att_kernel<<<dim3(256, 2), 224>>>();
    mpm_kernel<<<dim3(512, 2, 3), 256>>>(w_full, w_att, w_max_att, out);
}